// round 11
// baseline (speedup 1.0000x reference)
#include <cuda_runtime.h>
#include <cuda_fp16.h>
#include <cstdint>

typedef unsigned long long ull;

// ---------------- problem constants ----------------
#define NQ 8100
#define NK 8100
#define D_ 147
#define HO 90
#define H  96

#define KT    448          // fp16: [b(147)|s(147)|b(147)|kn cols|pad]
#define NR    8192
#define BM    128
#define BN    128
#define BK    64
#define KTILES 7           // 448/64

// ---------------- device scratch ----------------
__device__ __align__(256) __half g_A[(size_t)NR * KT];  // [qb | qs | qb | 1 1 0..]
__device__ __align__(256) __half g_B[(size_t)NR * KT];  // [kb | kb | ks | -kn/2 split]
__device__ ull   g_cand[NR];

// ---------------- helpers ----------------
__device__ __forceinline__ uint32_t smem_u32(const void* p) {
    uint32_t a;
    asm("{ .reg .u64 t; cvta.to.shared.u64 t, %1; cvt.u32.u64 %0, t; }" : "=r"(a) : "l"(p));
    return a;
}
__device__ __forceinline__ unsigned fkey(float f) {
    unsigned u = __float_as_uint(f);
    return (u & 0x80000000u) ? ~u : (u | 0x80000000u);
}
__device__ __forceinline__ void cp16(uint32_t dst, const void* src) {
    asm volatile("cp.async.cg.shared.global [%0], [%1], 16;" :: "r"(dst), "l"(src));
}
__device__ __forceinline__ void ldmatrix_x4(uint32_t* r, uint32_t addr) {
    asm volatile("ldmatrix.sync.aligned.m8n8.x4.shared.b16 {%0,%1,%2,%3}, [%4];"
                 : "=r"(r[0]), "=r"(r[1]), "=r"(r[2]), "=r"(r[3]) : "r"(addr));
}
__device__ __forceinline__ void mma_f16(float* c, const uint32_t* a, uint32_t b0, uint32_t b1) {
    asm volatile(
        "mma.sync.aligned.m16n8k16.row.col.f32.f16.f16.f32 "
        "{%0,%1,%2,%3}, {%4,%5,%6,%7}, {%8,%9}, {%0,%1,%2,%3};"
        : "+f"(c[0]), "+f"(c[1]), "+f"(c[2]), "+f"(c[3])
        : "r"(a[0]), "r"(a[1]), "r"(a[2]), "r"(a[3]), "r"(b0), "r"(b1));
}

// ---------------- element generators ----------------
__device__ __forceinline__ __half gen_A_elem(const float* __restrict__ query, int p, int k) {
    if (k == 441 || k == 442) return __float2half_rn(1.0f);
    if (p >= NQ || k >= 441) return __float2half_rn(0.0f);
    int term = 0, kk = k;
    if (k >= 294)      { term = 2; kk = k - 294; }
    else if (k >= 147) { term = 1; kk = k - 147; }
    int c  = kk / 49;
    int rr = kk - c * 49;
    int i  = rr / 7;
    int j  = rr - i * 7;
    int pi = p / HO;
    int pj = p - pi * HO;
    float x = query[c * (H * H) + (pi + i) * H + (pj + j)];
    __half b = __float2half_rn(x);
    return (term == 1) ? __float2half_rn(x - __half2float(b)) : b;
}
__device__ __forceinline__ __half gen_B_elem(const float* __restrict__ key, int p, int k) {
    if (p >= NK || k >= 441) return __float2half_rn(0.0f);
    int term = 0, kk = k;
    if (k >= 294)      { term = 2; kk = k - 294; }
    else if (k >= 147) { term = 1; kk = k - 147; }
    float x = key[p * D_ + kk];
    __half b = __float2half_rn(x);
    return (term == 2) ? __float2half_rn(x - __half2float(b)) : b;
}

// ---------------- fused prep: A and B vec8, plus g_cand init ----------------
__global__ void prep_AB_kernel(const float* __restrict__ query,
                               const float* __restrict__ key) {
    int t = blockIdx.x * 256 + threadIdx.x;          // t < NR*KT/8
    int p  = t / (KT / 8);
    int k0 = (t - p * (KT / 8)) * 8;
    __half va[8], vb[8];
    #pragma unroll
    for (int j = 0; j < 8; ++j) {
        va[j] = gen_A_elem(query, p, k0 + j);
        vb[j] = gen_B_elem(key,   p, k0 + j);
    }
    *reinterpret_cast<uint4*>(&g_A[(size_t)p * KT + k0]) = *reinterpret_cast<uint4*>(va);
    *reinterpret_cast<uint4*>(&g_B[(size_t)p * KT + k0]) = *reinterpret_cast<uint4*>(vb);
    if (t < NR) g_cand[t] = 0xFFFFFFFFFFFFFFFFull;
}

// kn -> B pad cols (after prep_AB); sentinel for pad rows
__global__ void prep_kn_kernel(const float* __restrict__ key) {
    int row  = blockIdx.x * 8 + (threadIdx.x >> 5);
    int lane = threadIdx.x & 31;
    if (row >= NR) return;
    if (row >= NK) {
        if (lane == 0) g_B[(size_t)row * KT + 441] = __float2half_rn(-60000.0f);
        return;
    }
    float s = 0.0f;
    for (int d = lane; d < D_; d += 32) {
        float v = key[row * D_ + d];
        s = fmaf(v, v, s);
    }
    #pragma unroll
    for (int off = 16; off > 0; off >>= 1)
        s += __shfl_down_sync(0xffffffffu, s, off);
    if (lane == 0) {
        float h  = -0.5f * s;
        __half b1 = __float2half_rn(h);
        __half b2 = __float2half_rn(h - __half2float(b1));
        g_B[(size_t)row * KT + 441] = b1;
        g_B[(size_t)row * KT + 442] = b2;
    }
}

// ---------------- main mma.sync fp16 GEMM + argmax(acc) ----------------
// smem: 3 x (As 16KB | Bs 16KB)
#define BUF_BYTES 32768
#define SMEM_TOTAL (3 * BUF_BYTES)

__global__ __launch_bounds__(256, 2) void nn_mma_kernel() {
    extern __shared__ __align__(128) char smem[];
    uint32_t sb = smem_u32(smem);

    const int tid = threadIdx.x;
    const int l   = tid & 31;
    const int wid = tid >> 5;
    const int wm  = wid & 3;    // 4 M-warps (32 rows each)
    const int wn  = wid >> 2;   // 2 N-warps (64 cols each)
    const int m0  = blockIdx.x * BM;
    const int n0  = blockIdx.y * BN;

    const __half* Ag = g_A + (size_t)m0 * KT;
    const __half* Bg = g_B + (size_t)n0 * KT;

    const int a_r  = (l & 7) | (((l >> 3) & 1) << 3);
    const int a_kh = (l >> 4) & 1;
    const int b_r  = (l & 7) | (((l >> 4) & 1) << 3);
    const int b_kh = (l >> 3) & 1;

    float acc[2][8][4];
    #pragma unroll
    for (int mi = 0; mi < 2; ++mi)
        #pragma unroll
        for (int ni = 0; ni < 8; ++ni)
            #pragma unroll
            for (int c = 0; c < 4; ++c) acc[mi][ni][c] = 0.0f;

    auto issue = [&](int kt) {
        uint32_t ab = sb + (uint32_t)(kt % 3) * BUF_BYTES;
        uint32_t bb = ab + 16384;
        const __half* As = Ag + kt * BK;
        const __half* Bs = Bg + kt * BK;
        #pragma unroll
        for (int i = tid; i < 1024; i += 256) {
            int r = i >> 3, c = i & 7;
            uint32_t off = ((uint32_t)r << 7) | ((uint32_t)(c ^ (r & 7)) << 4);
            cp16(ab + off, As + (size_t)r * KT + c * 8);
            cp16(bb + off, Bs + (size_t)r * KT + c * 8);
        }
        asm volatile("cp.async.commit_group;" ::: "memory");
    };

    issue(0);
    issue(1);

    for (int kt = 0; kt < KTILES; ++kt) {
        if (kt + 1 < KTILES) {
            asm volatile("cp.async.wait_group 1;" ::: "memory");
        } else {
            asm volatile("cp.async.wait_group 0;" ::: "memory");
        }
        __syncthreads();

        if (kt + 2 < KTILES) issue(kt + 2);

        uint32_t ab = sb + (uint32_t)(kt % 3) * BUF_BYTES;
        uint32_t bb = ab + 16384;

        #pragma unroll
        for (int ks = 0; ks < 4; ++ks) {
            uint32_t a[2][4];
            #pragma unroll
            for (int mi = 0; mi < 2; ++mi) {
                int row = wm * 32 + mi * 16 + a_r;
                uint32_t chunk = (uint32_t)((ks * 2 + a_kh) ^ (row & 7));
                ldmatrix_x4(a[mi], ab + ((uint32_t)row << 7) + (chunk << 4));
            }
            #pragma unroll
            for (int nj = 0; nj < 4; ++nj) {
                uint32_t b4[4];
                int nrow = wn * 64 + nj * 16 + b_r;
                uint32_t chunk = (uint32_t)((ks * 2 + b_kh) ^ (nrow & 7));
                ldmatrix_x4(b4, bb + ((uint32_t)nrow << 7) + (chunk << 4));
                #pragma unroll
                for (int mi = 0; mi < 2; ++mi) {
                    mma_f16(acc[mi][2 * nj],     a[mi], b4[0], b4[1]);
                    mma_f16(acc[mi][2 * nj + 1], a[mi], b4[2], b4[3]);
                }
            }
        }
        // no trailing sync: next iteration's sync protects buffer reuse
    }

    // ---- argmax(acc) epilogue (kn folded into GEMM) ----
    const int q = l & 3, g = l >> 2;
    float best[4];
    int   bidx[4];
    #pragma unroll
    for (int s = 0; s < 4; ++s) { best[s] = -3.402823466e38f; bidx[s] = 0; }

    #pragma unroll
    for (int mi = 0; mi < 2; ++mi) {
        #pragma unroll
        for (int ni = 0; ni < 8; ++ni) {
            int col0 = n0 + wn * 64 + ni * 8 + q * 2;
            #pragma unroll
            for (int h = 0; h < 2; ++h) {
                int s = mi * 2 + h;
                float a0 = acc[mi][ni][h * 2];
                float a1 = acc[mi][ni][h * 2 + 1];
                if (a0 > best[s]) { best[s] = a0; bidx[s] = col0; }
                if (a1 > best[s]) { best[s] = a1; bidx[s] = col0 + 1; }
            }
        }
    }

    #pragma unroll
    for (int s = 0; s < 4; ++s) {
        float b = best[s];
        int   i = bidx[s];
        #pragma unroll
        for (int off = 1; off <= 2; off <<= 1) {
            float ob = __shfl_xor_sync(0xffffffffu, b, off);
            int   oi = __shfl_xor_sync(0xffffffffu, i, off);
            if (ob > b || (ob == b && oi < i)) { b = ob; i = oi; }
        }
        if (q == 0) {
            int row = m0 + wm * 32 + (s >> 1) * 16 + (s & 1) * 8 + g;
            if (row < NQ)
                atomicMin(&g_cand[row], (((ull)fkey(-b)) << 32) | (unsigned)i);
        }
    }
}

// ---------------- fold v2: thread per (pixel, channel, pj-parity) ----------------
// 96*96*3*2 = 55296 threads; pj-parity halves combined via shfl.
__global__ void fold_kernel(const float* __restrict__ value, float* __restrict__ out) {
    int t = blockIdx.x * 128 + threadIdx.x;
    if (t >= H * H * 6) return;
    int half = t & 1;
    int c    = (t >> 1) % 3;
    int pix  = t / 6;
    int y = pix / H, x = pix - y * H;

    int pi0 = max(0, y - 6), pi1 = min(HO - 1, y);
    int pj0 = max(0, x - 6), pj1 = min(HO - 1, x);

    float s = 0.0f;
    for (int pi = pi0; pi <= pi1; ++pi) {
        int rowOff = c * 49 + (y - pi) * 7;
        #pragma unroll
        for (int pj = pj0 + half; pj <= pj1; pj += 2) {
            int row = (int)(unsigned)(g_cand[pi * HO + pj] & 0xffffffffull);
            s += __ldg(value + row * D_ + rowOff + (x - pj));
        }
    }
    // combine the two pj-parity halves (adjacent lanes, same (pix,c))
    s += __shfl_down_sync(0xffffffffu, s, 1);
    if (half == 0) {
        float inv = 1.0f / (float)((pi1 - pi0 + 1) * (pj1 - pj0 + 1));
        out[c * (H * H) + pix] = s * inv;
    }
}

// ---------------- launch ----------------
extern "C" void kernel_launch(void* const* d_in, const int* in_sizes, int n_in,
                              void* d_out, int out_size) {
    const float* query = (const float*)d_in[0];
    const float* key   = (const float*)d_in[1];
    const float* value = (const float*)d_in[2];
    float* out = (float*)d_out;

    {
        int n8 = NR * KT / 8;                      // 458,752 threads
        prep_AB_kernel<<<n8 / 256, 256>>>(query, key);
        prep_kn_kernel<<<NR / 8, 256>>>(key);      // overwrites B pad cols
    }
    {
        cudaFuncSetAttribute(nn_mma_kernel,
                             cudaFuncAttributeMaxDynamicSharedMemorySize, SMEM_TOTAL);
        dim3 grid(NR / BM, NR / BN);               // 64 x 64
        nn_mma_kernel<<<grid, 256, SMEM_TOTAL>>>();
    }
    {
        int n = H * H * 6;                         // 55,296
        fold_kernel<<<(n + 127) / 128, 128>>>(value, out);
    }
}

// round 12
// speedup vs baseline: 1.0035x; 1.0035x over previous
#include <cuda_runtime.h>
#include <cuda_fp16.h>
#include <cstdint>

typedef unsigned long long ull;

// ---------------- problem constants ----------------
#define NQ 8100
#define NK 8100
#define D_ 147
#define HO 90
#define H  96
#define NPIX (H * H)       // 9216

#define KT    448          // fp16: [b(147)|s(147)|b(147)|kn cols|pad]
#define NR    8192
#define BM    128
#define BN    128
#define BK    64
#define KTILES 7           // 448/64

// ---------------- device scratch ----------------
__device__ __align__(256) __half g_A[(size_t)NR * KT];  // [qb | qs | qb | 1 1 0..]
__device__ __align__(256) __half g_B[(size_t)NR * KT];  // [kb | kb | ks | -kn/2 split]
__device__ ull   g_cand[NR];
__device__ float g_acc[3 * NPIX];                        // fold accumulator

// ---------------- helpers ----------------
__device__ __forceinline__ uint32_t smem_u32(const void* p) {
    uint32_t a;
    asm("{ .reg .u64 t; cvta.to.shared.u64 t, %1; cvt.u32.u64 %0, t; }" : "=r"(a) : "l"(p));
    return a;
}
__device__ __forceinline__ unsigned fkey(float f) {
    unsigned u = __float_as_uint(f);
    return (u & 0x80000000u) ? ~u : (u | 0x80000000u);
}
__device__ __forceinline__ void cp16(uint32_t dst, const void* src) {
    asm volatile("cp.async.cg.shared.global [%0], [%1], 16;" :: "r"(dst), "l"(src));
}
__device__ __forceinline__ void ldmatrix_x4(uint32_t* r, uint32_t addr) {
    asm volatile("ldmatrix.sync.aligned.m8n8.x4.shared.b16 {%0,%1,%2,%3}, [%4];"
                 : "=r"(r[0]), "=r"(r[1]), "=r"(r[2]), "=r"(r[3]) : "r"(addr));
}
__device__ __forceinline__ void mma_f16(float* c, const uint32_t* a, uint32_t b0, uint32_t b1) {
    asm volatile(
        "mma.sync.aligned.m16n8k16.row.col.f32.f16.f16.f32 "
        "{%0,%1,%2,%3}, {%4,%5,%6,%7}, {%8,%9}, {%0,%1,%2,%3};"
        : "+f"(c[0]), "+f"(c[1]), "+f"(c[2]), "+f"(c[3])
        : "r"(a[0]), "r"(a[1]), "r"(a[2]), "r"(a[3]), "r"(b0), "r"(b1));
}

// ---------------- element generators ----------------
__device__ __forceinline__ __half gen_A_elem(const float* __restrict__ query, int p, int k) {
    if (k == 441 || k == 442) return __float2half_rn(1.0f);
    if (p >= NQ || k >= 441) return __float2half_rn(0.0f);
    int term = 0, kk = k;
    if (k >= 294)      { term = 2; kk = k - 294; }
    else if (k >= 147) { term = 1; kk = k - 147; }
    int c  = kk / 49;
    int rr = kk - c * 49;
    int i  = rr / 7;
    int j  = rr - i * 7;
    int pi = p / HO;
    int pj = p - pi * HO;
    float x = query[c * (H * H) + (pi + i) * H + (pj + j)];
    __half b = __float2half_rn(x);
    return (term == 1) ? __float2half_rn(x - __half2float(b)) : b;
}
__device__ __forceinline__ __half gen_B_elem(const float* __restrict__ key, int p, int k) {
    if (p >= NK || k >= 441) return __float2half_rn(0.0f);
    int term = 0, kk = k;
    if (k >= 294)      { term = 2; kk = k - 294; }
    else if (k >= 147) { term = 1; kk = k - 147; }
    float x = key[p * D_ + kk];
    __half b = __float2half_rn(x);
    return (term == 2) ? __float2half_rn(x - __half2float(b)) : b;
}

// ---------------- fused prep: A/B vec8 + kn pad cols + g_cand/g_acc init ----------------
__global__ void prep_AB_kernel(const float* __restrict__ query,
                               const float* __restrict__ key) {
    int t = blockIdx.x * 256 + threadIdx.x;          // t < NR*KT/8
    int p  = t / (KT / 8);
    int k0 = (t - p * (KT / 8)) * 8;
    __half va[8], vb[8];
    #pragma unroll
    for (int j = 0; j < 8; ++j) {
        va[j] = gen_A_elem(query, p, k0 + j);
        vb[j] = gen_B_elem(key,   p, k0 + j);
    }
    // thread owning k 440..447 also writes the kn columns (441,442)
    if (k0 == 440) {
        if (p < NK) {
            const float* kr = key + (size_t)p * D_;
            float s = 0.0f;
            #pragma unroll 7
            for (int d = 0; d < D_; ++d) {
                float v = __ldg(kr + d);
                s = fmaf(v, v, s);
            }
            float h = -0.5f * s;
            __half b1 = __float2half_rn(h);
            __half b2 = __float2half_rn(h - __half2float(b1));
            vb[1] = b1;
            vb[2] = b2;
        } else {
            vb[1] = __float2half_rn(-60000.0f);   // sentinel: pad rows never win
        }
    }
    *reinterpret_cast<uint4*>(&g_A[(size_t)p * KT + k0]) = *reinterpret_cast<uint4*>(va);
    *reinterpret_cast<uint4*>(&g_B[(size_t)p * KT + k0]) = *reinterpret_cast<uint4*>(vb);
    if (t < NR) g_cand[t] = 0xFFFFFFFFFFFFFFFFull;
    if (t < 3 * NPIX) g_acc[t] = 0.0f;
}

// ---------------- main mma.sync fp16 GEMM + argmax(acc) ----------------
// smem: 3 x (As 16KB | Bs 16KB)
#define BUF_BYTES 32768
#define SMEM_TOTAL (3 * BUF_BYTES)

__global__ __launch_bounds__(256, 2) void nn_mma_kernel() {
    extern __shared__ __align__(128) char smem[];
    uint32_t sb = smem_u32(smem);

    const int tid = threadIdx.x;
    const int l   = tid & 31;
    const int wid = tid >> 5;
    const int wm  = wid & 3;    // 4 M-warps (32 rows each)
    const int wn  = wid >> 2;   // 2 N-warps (64 cols each)
    const int m0  = blockIdx.x * BM;
    const int n0  = blockIdx.y * BN;

    const __half* Ag = g_A + (size_t)m0 * KT;
    const __half* Bg = g_B + (size_t)n0 * KT;

    const int a_r  = (l & 7) | (((l >> 3) & 1) << 3);
    const int a_kh = (l >> 4) & 1;
    const int b_r  = (l & 7) | (((l >> 4) & 1) << 3);
    const int b_kh = (l >> 3) & 1;

    float acc[2][8][4];
    #pragma unroll
    for (int mi = 0; mi < 2; ++mi)
        #pragma unroll
        for (int ni = 0; ni < 8; ++ni)
            #pragma unroll
            for (int c = 0; c < 4; ++c) acc[mi][ni][c] = 0.0f;

    auto issue = [&](int kt) {
        uint32_t ab = sb + (uint32_t)(kt % 3) * BUF_BYTES;
        uint32_t bb = ab + 16384;
        const __half* As = Ag + kt * BK;
        const __half* Bs = Bg + kt * BK;
        #pragma unroll
        for (int i = tid; i < 1024; i += 256) {
            int r = i >> 3, c = i & 7;
            uint32_t off = ((uint32_t)r << 7) | ((uint32_t)(c ^ (r & 7)) << 4);
            cp16(ab + off, As + (size_t)r * KT + c * 8);
            cp16(bb + off, Bs + (size_t)r * KT + c * 8);
        }
        asm volatile("cp.async.commit_group;" ::: "memory");
    };

    issue(0);
    issue(1);

    for (int kt = 0; kt < KTILES; ++kt) {
        if (kt + 1 < KTILES) {
            asm volatile("cp.async.wait_group 1;" ::: "memory");
        } else {
            asm volatile("cp.async.wait_group 0;" ::: "memory");
        }
        __syncthreads();

        if (kt + 2 < KTILES) issue(kt + 2);

        uint32_t ab = sb + (uint32_t)(kt % 3) * BUF_BYTES;
        uint32_t bb = ab + 16384;

        #pragma unroll
        for (int ks = 0; ks < 4; ++ks) {
            uint32_t a[2][4];
            #pragma unroll
            for (int mi = 0; mi < 2; ++mi) {
                int row = wm * 32 + mi * 16 + a_r;
                uint32_t chunk = (uint32_t)((ks * 2 + a_kh) ^ (row & 7));
                ldmatrix_x4(a[mi], ab + ((uint32_t)row << 7) + (chunk << 4));
            }
            #pragma unroll
            for (int nj = 0; nj < 4; ++nj) {
                uint32_t b4[4];
                int nrow = wn * 64 + nj * 16 + b_r;
                uint32_t chunk = (uint32_t)((ks * 2 + b_kh) ^ (nrow & 7));
                ldmatrix_x4(b4, bb + ((uint32_t)nrow << 7) + (chunk << 4));
                #pragma unroll
                for (int mi = 0; mi < 2; ++mi) {
                    mma_f16(acc[mi][2 * nj],     a[mi], b4[0], b4[1]);
                    mma_f16(acc[mi][2 * nj + 1], a[mi], b4[2], b4[3]);
                }
            }
        }
        // no trailing sync: next iteration's sync protects buffer reuse
    }

    // ---- argmax(acc) epilogue (kn folded into GEMM) ----
    const int q = l & 3, g = l >> 2;
    float best[4];
    int   bidx[4];
    #pragma unroll
    for (int s = 0; s < 4; ++s) { best[s] = -3.402823466e38f; bidx[s] = 0; }

    #pragma unroll
    for (int mi = 0; mi < 2; ++mi) {
        #pragma unroll
        for (int ni = 0; ni < 8; ++ni) {
            int col0 = n0 + wn * 64 + ni * 8 + q * 2;
            #pragma unroll
            for (int h = 0; h < 2; ++h) {
                int s = mi * 2 + h;
                float a0 = acc[mi][ni][h * 2];
                float a1 = acc[mi][ni][h * 2 + 1];
                if (a0 > best[s]) { best[s] = a0; bidx[s] = col0; }
                if (a1 > best[s]) { best[s] = a1; bidx[s] = col0 + 1; }
            }
        }
    }

    #pragma unroll
    for (int s = 0; s < 4; ++s) {
        float b = best[s];
        int   i = bidx[s];
        #pragma unroll
        for (int off = 1; off <= 2; off <<= 1) {
            float ob = __shfl_xor_sync(0xffffffffu, b, off);
            int   oi = __shfl_xor_sync(0xffffffffu, i, off);
            if (ob > b || (ob == b && oi < i)) { b = ob; i = oi; }
        }
        if (q == 0) {
            int row = m0 + wm * 32 + (s >> 1) * 16 + (s & 1) * 8 + g;
            if (row < NQ)
                atomicMin(&g_cand[row], (((ull)fkey(-b)) << 32) | (unsigned)i);
        }
    }
}

// ---------------- fold scatter: one warp per patch ----------------
__global__ void scatter_kernel(const float* __restrict__ value) {
    int w    = blockIdx.x * 8 + (threadIdx.x >> 5);   // patch index
    int lane = threadIdx.x & 31;
    if (w >= NQ) return;
    int row = (int)(unsigned)(g_cand[w] & 0xffffffffull);
    int pi = w / HO, pj = w - (w / HO) * HO;
    const float* vr = value + (size_t)row * D_;
    #pragma unroll
    for (int e = lane; e < D_; e += 32) {
        int c  = e / 49;
        int rr = e - c * 49;
        int i  = rr / 7;
        int j  = rr - i * 7;
        atomicAdd(&g_acc[c * NPIX + (pi + i) * H + (pj + j)], __ldg(vr + e));
    }
}

// ---------------- finalize: divide by analytic overlap count ----------------
__global__ void finalize_kernel(float* __restrict__ out) {
    int t = blockIdx.x * 256 + threadIdx.x;
    if (t >= 3 * NPIX) return;
    int pix = t % NPIX;
    int y = pix / H, x = pix - y * H;
    int npi = min(HO - 1, y) - max(0, y - 6) + 1;
    int npj = min(HO - 1, x) - max(0, x - 6) + 1;
    out[t] = g_acc[t] * (1.0f / (float)(npi * npj));
}

// ---------------- launch ----------------
extern "C" void kernel_launch(void* const* d_in, const int* in_sizes, int n_in,
                              void* d_out, int out_size) {
    const float* query = (const float*)d_in[0];
    const float* key   = (const float*)d_in[1];
    const float* value = (const float*)d_in[2];
    float* out = (float*)d_out;

    {
        int n8 = NR * KT / 8;                      // 458,752 threads
        prep_AB_kernel<<<n8 / 256, 256>>>(query, key);
    }
    {
        cudaFuncSetAttribute(nn_mma_kernel,
                             cudaFuncAttributeMaxDynamicSharedMemorySize, SMEM_TOTAL);
        dim3 grid(NR / BM, NR / BN);               // 64 x 64
        nn_mma_kernel<<<grid, 256, SMEM_TOTAL>>>();
    }
    {
        scatter_kernel<<<(NQ + 7) / 8, 256>>>(value);
        finalize_kernel<<<(3 * NPIX + 255) / 256, 256>>>(out);
    }
}

// round 13
// speedup vs baseline: 1.0053x; 1.0018x over previous
#include <cuda_runtime.h>
#include <cuda_fp16.h>
#include <cstdint>

typedef unsigned long long ull;

// ---------------- problem constants ----------------
#define NQ 8100
#define NK 8100
#define D_ 147
#define HO 90
#define H  96
#define NPIX (H * H)       // 9216

#define KT    448          // fp16: [b(147)|s(147)|b(147)|kn cols|pad]
#define NR    8192
#define BM    128
#define BN    128
#define BK    64
#define KTILES 7           // 448/64

// ---------------- device scratch ----------------
__device__ __align__(256) __half g_A[(size_t)NR * KT];  // [qb | qs | qb | 1 1 0..]
__device__ __align__(256) __half g_B[(size_t)NR * KT];  // [kb | kb | ks | -kn/2 split]
__device__ ull   g_cand[NR];

// ---------------- helpers ----------------
__device__ __forceinline__ uint32_t smem_u32(const void* p) {
    uint32_t a;
    asm("{ .reg .u64 t; cvta.to.shared.u64 t, %1; cvt.u32.u64 %0, t; }" : "=r"(a) : "l"(p));
    return a;
}
__device__ __forceinline__ unsigned fkey(float f) {
    unsigned u = __float_as_uint(f);
    return (u & 0x80000000u) ? ~u : (u | 0x80000000u);
}
__device__ __forceinline__ void cp16(uint32_t dst, const void* src) {
    asm volatile("cp.async.cg.shared.global [%0], [%1], 16;" :: "r"(dst), "l"(src));
}
__device__ __forceinline__ void ldmatrix_x4(uint32_t* r, uint32_t addr) {
    asm volatile("ldmatrix.sync.aligned.m8n8.x4.shared.b16 {%0,%1,%2,%3}, [%4];"
                 : "=r"(r[0]), "=r"(r[1]), "=r"(r[2]), "=r"(r[3]) : "r"(addr));
}
__device__ __forceinline__ void mma_f16(float* c, const uint32_t* a, uint32_t b0, uint32_t b1) {
    asm volatile(
        "mma.sync.aligned.m16n8k16.row.col.f32.f16.f16.f32 "
        "{%0,%1,%2,%3}, {%4,%5,%6,%7}, {%8,%9}, {%0,%1,%2,%3};"
        : "+f"(c[0]), "+f"(c[1]), "+f"(c[2]), "+f"(c[3])
        : "r"(a[0]), "r"(a[1]), "r"(a[2]), "r"(a[3]), "r"(b0), "r"(b1));
}

// ---------------- element generators ----------------
__device__ __forceinline__ __half gen_A_elem(const float* __restrict__ query, int p, int k) {
    if (k == 441 || k == 442) return __float2half_rn(1.0f);
    if (p >= NQ || k >= 441) return __float2half_rn(0.0f);
    int term = 0, kk = k;
    if (k >= 294)      { term = 2; kk = k - 294; }
    else if (k >= 147) { term = 1; kk = k - 147; }
    int c  = kk / 49;
    int rr = kk - c * 49;
    int i  = rr / 7;
    int j  = rr - i * 7;
    int pi = p / HO;
    int pj = p - pi * HO;
    float x = query[c * (H * H) + (pi + i) * H + (pj + j)];
    __half b = __float2half_rn(x);
    return (term == 1) ? __float2half_rn(x - __half2float(b)) : b;
}
__device__ __forceinline__ __half gen_B_elem(const float* __restrict__ key, int p, int k) {
    if (p >= NK || k >= 441) return __float2half_rn(0.0f);
    int term = 0, kk = k;
    if (k >= 294)      { term = 2; kk = k - 294; }
    else if (k >= 147) { term = 1; kk = k - 147; }
    float x = key[p * D_ + kk];
    __half b = __float2half_rn(x);
    return (term == 2) ? __float2half_rn(x - __half2float(b)) : b;
}

// ---------------- fused prep: A/B vec8 + kn pad cols + g_cand init + out zero ----------------
__global__ void prep_AB_kernel(const float* __restrict__ query,
                               const float* __restrict__ key,
                               float* __restrict__ out) {
    int t = blockIdx.x * 256 + threadIdx.x;          // t < NR*KT/8
    int p  = t / (KT / 8);
    int k0 = (t - p * (KT / 8)) * 8;
    __half va[8], vb[8];
    #pragma unroll
    for (int j = 0; j < 8; ++j) {
        va[j] = gen_A_elem(query, p, k0 + j);
        vb[j] = gen_B_elem(key,   p, k0 + j);
    }
    // thread owning k 440..447 also writes the kn columns (441,442)
    if (k0 == 440) {
        if (p < NK) {
            const float* kr = key + (size_t)p * D_;
            float s = 0.0f;
            #pragma unroll 7
            for (int d = 0; d < D_; ++d) {
                float v = __ldg(kr + d);
                s = fmaf(v, v, s);
            }
            float h = -0.5f * s;
            __half b1 = __float2half_rn(h);
            __half b2 = __float2half_rn(h - __half2float(b1));
            vb[1] = b1;
            vb[2] = b2;
        } else {
            vb[1] = __float2half_rn(-60000.0f);   // sentinel: pad rows never win
        }
    }
    *reinterpret_cast<uint4*>(&g_A[(size_t)p * KT + k0]) = *reinterpret_cast<uint4*>(va);
    *reinterpret_cast<uint4*>(&g_B[(size_t)p * KT + k0]) = *reinterpret_cast<uint4*>(vb);
    if (t < NR) g_cand[t] = 0xFFFFFFFFFFFFFFFFull;
    if (t < 3 * NPIX) out[t] = 0.0f;
}

// ---------------- main mma.sync fp16 GEMM + argmax(acc) ----------------
// smem: 3 x (As 16KB | Bs 16KB)
#define BUF_BYTES 32768
#define SMEM_TOTAL (3 * BUF_BYTES)

__global__ __launch_bounds__(256, 2) void nn_mma_kernel() {
    extern __shared__ __align__(128) char smem[];
    uint32_t sb = smem_u32(smem);

    const int tid = threadIdx.x;
    const int l   = tid & 31;
    const int wid = tid >> 5;
    const int wm  = wid & 3;    // 4 M-warps (32 rows each)
    const int wn  = wid >> 2;   // 2 N-warps (64 cols each)
    const int m0  = blockIdx.x * BM;
    const int n0  = blockIdx.y * BN;

    const __half* Ag = g_A + (size_t)m0 * KT;
    const __half* Bg = g_B + (size_t)n0 * KT;

    const int a_r  = (l & 7) | (((l >> 3) & 1) << 3);
    const int a_kh = (l >> 4) & 1;
    const int b_r  = (l & 7) | (((l >> 4) & 1) << 3);
    const int b_kh = (l >> 3) & 1;

    float acc[2][8][4];
    #pragma unroll
    for (int mi = 0; mi < 2; ++mi)
        #pragma unroll
        for (int ni = 0; ni < 8; ++ni)
            #pragma unroll
            for (int c = 0; c < 4; ++c) acc[mi][ni][c] = 0.0f;

    auto issue = [&](int kt) {
        uint32_t ab = sb + (uint32_t)(kt % 3) * BUF_BYTES;
        uint32_t bb = ab + 16384;
        const __half* As = Ag + kt * BK;
        const __half* Bs = Bg + kt * BK;
        #pragma unroll
        for (int i = tid; i < 1024; i += 256) {
            int r = i >> 3, c = i & 7;
            uint32_t off = ((uint32_t)r << 7) | ((uint32_t)(c ^ (r & 7)) << 4);
            cp16(ab + off, As + (size_t)r * KT + c * 8);
            cp16(bb + off, Bs + (size_t)r * KT + c * 8);
        }
        asm volatile("cp.async.commit_group;" ::: "memory");
    };

    issue(0);
    issue(1);

    for (int kt = 0; kt < KTILES; ++kt) {
        if (kt + 1 < KTILES) {
            asm volatile("cp.async.wait_group 1;" ::: "memory");
        } else {
            asm volatile("cp.async.wait_group 0;" ::: "memory");
        }
        __syncthreads();

        if (kt + 2 < KTILES) issue(kt + 2);

        uint32_t ab = sb + (uint32_t)(kt % 3) * BUF_BYTES;
        uint32_t bb = ab + 16384;

        #pragma unroll
        for (int ks = 0; ks < 4; ++ks) {
            uint32_t a[2][4];
            #pragma unroll
            for (int mi = 0; mi < 2; ++mi) {
                int row = wm * 32 + mi * 16 + a_r;
                uint32_t chunk = (uint32_t)((ks * 2 + a_kh) ^ (row & 7));
                ldmatrix_x4(a[mi], ab + ((uint32_t)row << 7) + (chunk << 4));
            }
            #pragma unroll
            for (int nj = 0; nj < 4; ++nj) {
                uint32_t b4[4];
                int nrow = wn * 64 + nj * 16 + b_r;
                uint32_t chunk = (uint32_t)((ks * 2 + b_kh) ^ (nrow & 7));
                ldmatrix_x4(b4, bb + ((uint32_t)nrow << 7) + (chunk << 4));
                #pragma unroll
                for (int mi = 0; mi < 2; ++mi) {
                    mma_f16(acc[mi][2 * nj],     a[mi], b4[0], b4[1]);
                    mma_f16(acc[mi][2 * nj + 1], a[mi], b4[2], b4[3]);
                }
            }
        }
        // no trailing sync: next iteration's sync protects buffer reuse
    }

    // ---- argmax(acc) epilogue (kn folded into GEMM) ----
    const int q = l & 3, g = l >> 2;
    float best[4];
    int   bidx[4];
    #pragma unroll
    for (int s = 0; s < 4; ++s) { best[s] = -3.402823466e38f; bidx[s] = 0; }

    #pragma unroll
    for (int mi = 0; mi < 2; ++mi) {
        #pragma unroll
        for (int ni = 0; ni < 8; ++ni) {
            int col0 = n0 + wn * 64 + ni * 8 + q * 2;
            #pragma unroll
            for (int h = 0; h < 2; ++h) {
                int s = mi * 2 + h;
                float a0 = acc[mi][ni][h * 2];
                float a1 = acc[mi][ni][h * 2 + 1];
                if (a0 > best[s]) { best[s] = a0; bidx[s] = col0; }
                if (a1 > best[s]) { best[s] = a1; bidx[s] = col0 + 1; }
            }
        }
    }

    #pragma unroll
    for (int s = 0; s < 4; ++s) {
        float b = best[s];
        int   i = bidx[s];
        #pragma unroll
        for (int off = 1; off <= 2; off <<= 1) {
            float ob = __shfl_xor_sync(0xffffffffu, b, off);
            int   oi = __shfl_xor_sync(0xffffffffu, i, off);
            if (ob > b || (ob == b && oi < i)) { b = ob; i = oi; }
        }
        if (q == 0) {
            int row = m0 + wm * 32 + (s >> 1) * 16 + (s & 1) * 8 + g;
            if (row < NQ)
                atomicMin(&g_cand[row], (((ull)fkey(-b)) << 32) | (unsigned)i);
        }
    }
}

// ---------------- fold scatter: one warp per patch, pre-divided atomics ----------------
__global__ void scatter_kernel(const float* __restrict__ value, float* __restrict__ out) {
    int w    = blockIdx.x * 8 + (threadIdx.x >> 5);   // patch index
    int lane = threadIdx.x & 31;
    if (w >= NQ) return;
    int row = (int)(unsigned)(g_cand[w] & 0xffffffffull);
    int pi = w / HO, pj = w - (w / HO) * HO;
    const float* vr = value + (size_t)row * D_;
    #pragma unroll
    for (int e = lane; e < D_; e += 32) {
        int c  = e / 49;
        int rr = e - c * 49;
        int i  = rr / 7;
        int j  = rr - i * 7;
        int y  = pi + i, x = pj + j;
        int npi = min(HO - 1, y) - max(0, y - 6) + 1;
        int npj = min(HO - 1, x) - max(0, x - 6) + 1;
        float inv = __frcp_rn((float)(npi * npj));
        atomicAdd(&out[c * NPIX + y * H + x], __ldg(vr + e) * inv);
    }
}

// ---------------- launch ----------------
extern "C" void kernel_launch(void* const* d_in, const int* in_sizes, int n_in,
                              void* d_out, int out_size) {
    const float* query = (const float*)d_in[0];
    const float* key   = (const float*)d_in[1];
    const float* value = (const float*)d_in[2];
    float* out = (float*)d_out;

    {
        int n8 = NR * KT / 8;                      // 458,752 threads
        prep_AB_kernel<<<n8 / 256, 256>>>(query, key, out);
    }
    {
        cudaFuncSetAttribute(nn_mma_kernel,
                             cudaFuncAttributeMaxDynamicSharedMemorySize, SMEM_TOTAL);
        dim3 grid(NR / BM, NR / BN);               // 64 x 64
        nn_mma_kernel<<<grid, 256, SMEM_TOTAL>>>();
    }
    {
        scatter_kernel<<<(NQ + 7) / 8, 256>>>(value, out);
    }
}